// round 9
// baseline (speedup 1.0000x reference)
#include <cuda_runtime.h>
#include <cuda_bf16.h>
#include <cstdint>

// Problem constants: T=32768, E=256, K=8, D=8, r=2
#define E_EXPERTS 256
#define D_DEVS    8
#define K_TOPK    8
#define E_PER_DEV (E_EXPERTS / D_DEVS)   // 32
#define TOK_PER_TILE 32                  // tile = 32 tokens (8 warps x 4)
#define TILE_FLOATS (D_DEVS * TOK_PER_TILE * E_PER_DEV)   // 8192 = 32KB

// One block builds TWO 32-token tiles in one 32KB smem buffer.
// Zeros + invperm computed once; tile B only re-zeros the 256 positions
// tile A touched. All dense global writes go out via TMA bulk stores.
__global__ __launch_bounds__(256) void moe_remap_pipe(
    const float* __restrict__ topk,     // [T, E]
    const int*   __restrict__ mapping,  // [E, D] one-hot
    const int*   __restrict__ meta,     // [T, K]
    float*       __restrict__ out,      // [D, T, 32]
    float*       __restrict__ mask,     // [T/2, D]
    int T)
{
    __shared__ __align__(128) float sdata[TILE_FLOATS];   // 32KB
    __shared__ int wcnt_s[64];
    __shared__ int C_s[64];
    __shared__ int invperm_s[E_EXPERTS];

    const int tid  = threadIdx.x;
    const int lane = tid & 31;
    const int warp = tid >> 5;

    const int tA = blockIdx.x * 2;          // two consecutive tiles
    const int tB = tA + 1;
    const int t0A = tA * TOK_PER_TILE + warp * 4;   // warp's first token, tile A
    const int t0B = tB * TOK_PER_TILE + warp * 4;

    // ---- issue all global loads up front (MLP) ----
    const int eA = meta[t0A * K_TOPK + lane];
    const int eB = meta[t0B * K_TOPK + lane];

    const int4 a4 = reinterpret_cast<const int4*>(mapping)[tid * 2];
    const int4 b4 = reinterpret_cast<const int4*>(mapping)[tid * 2 + 1];

    const int tl = lane >> 3;                                 // local token 0..3
    const float vA = topk[(t0A + tl) * E_EXPERTS + eA];
    const float vB = topk[(t0B + tl) * E_EXPERTS + eB];

    // ---- invperm (once per block): argmax + ballot counts ----
    int v8[8] = {a4.x, a4.y, a4.z, a4.w, b4.x, b4.y, b4.z, b4.w};
    int best = v8[0], d = 0;
#pragma unroll
    for (int i = 1; i < D_DEVS; i++)
        if (v8[i] > best) { best = v8[i]; d = i; }            // first max wins

    const unsigned lt = (1u << lane) - 1u;
    int within = 0, mycnt = 0;
#pragma unroll
    for (int d2 = 0; d2 < D_DEVS; d2++) {
        unsigned b = __ballot_sync(0xffffffffu, d == d2);
        if (d2 == d)    within = __popc(b & lt);
        if (lane == d2) mycnt  = __popc(b);
    }
    if (lane < D_DEVS) wcnt_s[warp * 8 + lane] = mycnt;

    // ---- zero the 32KB buffer (once): 8 x STS.128 per thread ----
    {
        float4* s4 = reinterpret_cast<float4*>(sdata);
        const float4 z = make_float4(0.f, 0.f, 0.f, 0.f);
#pragma unroll
        for (int i = 0; i < 8; i++) s4[tid + 256 * i] = z;
    }
    __syncthreads();

    // warp 0: exclusive scan of 64 counts in (device*8 + warp) order
    if (warp == 0) {
        int x0 = wcnt_s[(lane & 7) * 8 + (lane >> 3)];
        int x1 = wcnt_s[((lane + 32) & 7) * 8 + ((lane + 32) >> 3)];
        int i0 = x0, i1 = x1;
#pragma unroll
        for (int o = 1; o < 32; o <<= 1) {
            int y0 = __shfl_up_sync(0xffffffffu, i0, o);
            int y1 = __shfl_up_sync(0xffffffffu, i1, o);
            if (lane >= o) { i0 += y0; i1 += y1; }
        }
        const int tot0 = __shfl_sync(0xffffffffu, i0, 31);
        C_s[lane]      = i0 - x0;
        C_s[lane + 32] = i1 - x1 + tot0;
    }
    __syncthreads();
    invperm_s[tid] = C_s[d * 8 + warp] + within;
    __syncthreads();

    uint32_t saddr;
    asm("{ .reg .u64 t; cvta.to.shared.u64 t, %1; cvt.u32.u64 %0, t; }"
        : "=r"(saddr) : "l"(sdata));

    // ================= tile A =================
    const int pA = invperm_s[eA];
    const int dA = pA >> 5, jA = pA & 31;
    const int posA = dA * (TOK_PER_TILE * E_PER_DEV) + (warp * 4 + tl) * E_PER_DEV + jA;
    sdata[posA] = vA;

    {   // mask rows for tile A (pairs 2q, 2q+1 of quad = tA*8+warp)
        const unsigned pm = (lane < 16) ? 0x0000ffffu : 0xffff0000u;
        const unsigned r  = __reduce_or_sync(pm, 1u << dA);
        const unsigned hr = __shfl_sync(0xffffffffu, r, 16);
        if (lane < 16) {
            const unsigned bits = (lane < 8) ? r : hr;
            mask[(tA * 8 + warp) * 16 + lane] = ((bits >> (lane & 7)) & 1u) ? 1.0f : 0.0f;
        }
    }

    asm volatile("fence.proxy.async.shared::cta;" ::: "memory");
    __syncthreads();
    if (tid == 0) {
#pragma unroll
        for (int dd = 0; dd < D_DEVS; dd++) {
            float* gdst = out + dd * (T * E_PER_DEV) + tA * (TOK_PER_TILE * E_PER_DEV);
            asm volatile(
                "cp.async.bulk.global.shared::cta.bulk_group [%0], [%1], %2;"
                :: "l"(gdst),
                   "r"(saddr + dd * (TOK_PER_TILE * E_PER_DEV * 4)),
                   "r"(TOK_PER_TILE * E_PER_DEV * 4)
                : "memory");
        }
        asm volatile("cp.async.bulk.commit_group;" ::: "memory");
        // wait only for TMA to finish READING smem (writes drain async)
        asm volatile("cp.async.bulk.wait_group.read 0;" ::: "memory");
    }

    // mask rows for tile B (independent of buffer; do while TMA drains)
    const int pB = invperm_s[eB];
    const int dB = pB >> 5, jB = pB & 31;
    {
        const unsigned pm = (lane < 16) ? 0x0000ffffu : 0xffff0000u;
        const unsigned r  = __reduce_or_sync(pm, 1u << dB);
        const unsigned hr = __shfl_sync(0xffffffffu, r, 16);
        if (lane < 16) {
            const unsigned bits = (lane < 8) ? r : hr;
            mask[(tB * 8 + warp) * 16 + lane] = ((bits >> (lane & 7)) & 1u) ? 1.0f : 0.0f;
        }
    }

    __syncthreads();          // tile A smem reads complete block-wide

    // ================= tile B =================
    sdata[posA] = 0.f;        // undo tile A's scatter (256 positions total)
    __syncthreads();          // zeros before new scatters (positions may collide)

    const int posB = dB * (TOK_PER_TILE * E_PER_DEV) + (warp * 4 + tl) * E_PER_DEV + jB;
    sdata[posB] = vB;

    asm volatile("fence.proxy.async.shared::cta;" ::: "memory");
    __syncthreads();
    if (tid == 0) {
#pragma unroll
        for (int dd = 0; dd < D_DEVS; dd++) {
            float* gdst = out + dd * (T * E_PER_DEV) + tB * (TOK_PER_TILE * E_PER_DEV);
            asm volatile(
                "cp.async.bulk.global.shared::cta.bulk_group [%0], [%1], %2;"
                :: "l"(gdst),
                   "r"(saddr + dd * (TOK_PER_TILE * E_PER_DEV * 4)),
                   "r"(TOK_PER_TILE * E_PER_DEV * 4)
                : "memory");
        }
        asm volatile("cp.async.bulk.commit_group;" ::: "memory");
        asm volatile("cp.async.bulk.wait_group.read 0;" ::: "memory");
    }
    __syncthreads();          // protect smem until TMA reads done
}

extern "C" void kernel_launch(void* const* d_in, const int* in_sizes, int n_in,
                              void* d_out, int out_size) {
    const float* topk    = (const float*)d_in[0];   // [1,1,T,E]
    const int*   mapping = (const int*)  d_in[1];   // [1,1,E,D]
    const int*   meta    = (const int*)  d_in[2];   // [1,1,T,K]

    const int T = in_sizes[0] / E_EXPERTS;          // 32768

    float* out  = (float*)d_out;                            // [D, T, 32]
    float* mask = out + (size_t)D_DEVS * T * E_PER_DEV;     // [T/2, D]

    const int blocks = T / (2 * TOK_PER_TILE);      // 512 (2 tiles per block)
    moe_remap_pipe<<<blocks, 256>>>(topk, mapping, meta, out, mask, T);
}

// round 10
// speedup vs baseline: 1.3400x; 1.3400x over previous
#include <cuda_runtime.h>
#include <cuda_bf16.h>
#include <cstdint>

// Problem constants: T=32768, E=256, K=8, D=8, r=2
#define E_EXPERTS 256
#define D_DEVS    8
#define K_TOPK    8
#define E_PER_DEV (E_EXPERTS / D_DEVS)   // 32
#define TOK_PER_TILE 16                  // tile = 16 tokens (4 warps x 4)
#define TILE_FLOATS (D_DEVS * TOK_PER_TILE * E_PER_DEV)   // 4096 = 16KB

// Small-granularity build kernel: block = 128 threads = one 16-token tile.
// Build [8][16tok][32] slice in smem, TMA bulk-store 8 x 2KB plane slices.
__global__ __launch_bounds__(128) void moe_remap_small(
    const float* __restrict__ topk,     // [T, E]
    const int*   __restrict__ mapping,  // [E, D] one-hot
    const int*   __restrict__ meta,     // [T, K]
    float*       __restrict__ out,      // [D, T, 32]
    float*       __restrict__ mask,     // [T/2, D]
    int T)
{
    __shared__ __align__(128) float sdata[TILE_FLOATS];   // 16KB
    __shared__ int wcnt_s[64];          // [group 0..7][device 0..7]
    __shared__ int C_s[64];             // exclusive prefix, order f = d*8+g
    __shared__ short invperm_s[E_EXPERTS];

    const int tid  = threadIdx.x;       // 0..127
    const int lane = tid & 31;
    const int warp = tid >> 5;          // 0..3
    const int blkT = blockIdx.x * TOK_PER_TILE;
    const int t0   = blkT + warp * 4;   // warp's first token
    const int quad = blockIdx.x * 4 + warp;

    // ---- all global loads up front ----
    const int e = meta[t0 * K_TOPK + lane];          // 32 contiguous ints/warp

    // two experts per thread: e0 = tid, e1 = tid + 128
    const int4 a0 = reinterpret_cast<const int4*>(mapping)[tid * 2];
    const int4 b0 = reinterpret_cast<const int4*>(mapping)[tid * 2 + 1];
    const int4 a1 = reinterpret_cast<const int4*>(mapping)[(tid + 128) * 2];
    const int4 b1 = reinterpret_cast<const int4*>(mapping)[(tid + 128) * 2 + 1];

    const int tl = lane >> 3;                        // local token 0..3
    const float gv = topk[(t0 + tl) * E_EXPERTS + e];

    // ---- device of each expert (argmax, first max wins) ----
    int va[8] = {a0.x, a0.y, a0.z, a0.w, b0.x, b0.y, b0.z, b0.w};
    int vb[8] = {a1.x, a1.y, a1.z, a1.w, b1.x, b1.y, b1.z, b1.w};
    int best0 = va[0], d0 = 0, best1 = vb[0], d1 = 0;
#pragma unroll
    for (int i = 1; i < D_DEVS; i++) {
        if (va[i] > best0) { best0 = va[i]; d0 = i; }
        if (vb[i] > best1) { best1 = vb[i]; d1 = i; }
    }

    // ---- ballots: within-warp rank + per-(group, device) counts ----
    // groups: half0 (experts 0..127) -> g = warp; half1 -> g = 4 + warp
    const unsigned lt = (1u << lane) - 1u;
    int within0 = 0, within1 = 0, cnt0 = 0, cnt1 = 0;
#pragma unroll
    for (int d2 = 0; d2 < D_DEVS; d2++) {
        unsigned m0 = __ballot_sync(0xffffffffu, d0 == d2);
        unsigned m1 = __ballot_sync(0xffffffffu, d1 == d2);
        if (d2 == d0)   within0 = __popc(m0 & lt);
        if (d2 == d1)   within1 = __popc(m1 & lt);
        if (lane == d2) { cnt0 = __popc(m0); cnt1 = __popc(m1); }
    }
    if (lane < D_DEVS) {
        wcnt_s[warp * 8 + lane]       = cnt0;
        wcnt_s[(4 + warp) * 8 + lane] = cnt1;
    }

    // ---- zero the 16KB tile: 4096 f4 / 128 thr = 8 STS.128 each ----
    {
        float4* s4 = reinterpret_cast<float4*>(sdata);
        const float4 z = make_float4(0.f, 0.f, 0.f, 0.f);
#pragma unroll
        for (int i = 0; i < 8; i++) s4[tid + 128 * i] = z;
    }
    __syncthreads();   // wcnt + zeros visible

    // ---- warp 0: exclusive scan over 64 counts, order f = d*8 + g ----
    if (warp == 0) {
        int x0 = wcnt_s[(lane & 7) * 8 + (lane >> 3)];               // f = lane
        int x1 = wcnt_s[((lane + 32) & 7) * 8 + ((lane + 32) >> 3)]; // f = lane+32
        int i0 = x0, i1 = x1;
#pragma unroll
        for (int o = 1; o < 32; o <<= 1) {
            int y0 = __shfl_up_sync(0xffffffffu, i0, o);
            int y1 = __shfl_up_sync(0xffffffffu, i1, o);
            if (lane >= o) { i0 += y0; i1 += y1; }
        }
        const int tot0 = __shfl_sync(0xffffffffu, i0, 31);
        C_s[lane]      = i0 - x0;
        C_s[lane + 32] = i1 - x1 + tot0;
    }
    __syncthreads();   // C ready

    invperm_s[tid]       = (short)(C_s[d0 * 8 + warp]     + within0);
    invperm_s[tid + 128] = (short)(C_s[d1 * 8 + 4 + warp] + within1);
    __syncthreads();   // invperm table ready

    // ---- scatter into smem + masks ----
    const int p  = invperm_s[e];
    const int ds = p >> 5, js = p & 31;
    sdata[ds * (TOK_PER_TILE * E_PER_DEV) + (warp * 4 + tl) * E_PER_DEV + js] = gv;

    {
        const unsigned pm = (lane < 16) ? 0x0000ffffu : 0xffff0000u;
        const unsigned r  = __reduce_or_sync(pm, 1u << ds);
        const unsigned hr = __shfl_sync(0xffffffffu, r, 16);
        if (lane < 16) {
            const unsigned bits = (lane < 8) ? r : hr;
            mask[quad * 16 + lane] = ((bits >> (lane & 7)) & 1u) ? 1.0f : 0.0f;
        }
    }

    // ---- publish to async proxy, bulk-store 8 x 2KB plane slices ----
    asm volatile("fence.proxy.async.shared::cta;" ::: "memory");
    __syncthreads();

    if (tid == 0) {
        uint32_t saddr;
        asm("{ .reg .u64 t; cvta.to.shared.u64 t, %1; cvt.u32.u64 %0, t; }"
            : "=r"(saddr) : "l"(sdata));
#pragma unroll
        for (int dd = 0; dd < D_DEVS; dd++) {
            float* gdst = out + dd * (T * E_PER_DEV) + blkT * E_PER_DEV;
            asm volatile(
                "cp.async.bulk.global.shared::cta.bulk_group [%0], [%1], %2;"
                :: "l"(gdst),
                   "r"(saddr + dd * (TOK_PER_TILE * E_PER_DEV * 4)),
                   "r"(TOK_PER_TILE * E_PER_DEV * 4)
                : "memory");
        }
        asm volatile("cp.async.bulk.commit_group;" ::: "memory");
        // hold CTA (and its smem) alive until TMA has READ the data;
        // global writes drain asynchronously after block exit
        asm volatile("cp.async.bulk.wait_group.read 0;" ::: "memory");
    }
}

extern "C" void kernel_launch(void* const* d_in, const int* in_sizes, int n_in,
                              void* d_out, int out_size) {
    const float* topk    = (const float*)d_in[0];   // [1,1,T,E]
    const int*   mapping = (const int*)  d_in[1];   // [1,1,E,D]
    const int*   meta    = (const int*)  d_in[2];   // [1,1,T,K]

    const int T = in_sizes[0] / E_EXPERTS;          // 32768

    float* out  = (float*)d_out;                            // [D, T, 32]
    float* mask = out + (size_t)D_DEVS * T * E_PER_DEV;     // [T/2, D]

    const int blocks = T / TOK_PER_TILE;            // 2048
    moe_remap_small<<<blocks, 128>>>(topk, mapping, meta, out, mask, T);
}

// round 11
// speedup vs baseline: 1.3434x; 1.0025x over previous
#include <cuda_runtime.h>
#include <cuda_bf16.h>
#include <cstdint>

// Problem constants: T=32768, E=256, K=8, D=8, r=2
#define E_EXPERTS 256
#define D_DEVS    8
#define K_TOPK    8
#define E_PER_DEV (E_EXPERTS / D_DEVS)   // 32
#define TOK_PER_BLK 64                   // 8 warps x 8 tokens
#define TILE_FLOATS (D_DEVS * TOK_PER_BLK * E_PER_DEV)   // 16384 = 64KB? no: 8*64*32=16384 floats = 64KB

// NOTE: 8*64*32 floats = 16384 floats = 64KB is too big; use half-planes?
// Recompute: we need [D][64 tok][32] = 16384 floats = 64KB. Too much for 6/SM.
// Instead: [D][64][32] but store as 2 halves? Simpler: 32KB buffer covering
// 32 tokens per half, two TMA flushes — but that reintroduces serialization.
// Resolution: keep 64KB tile, 256 threads, 2 blocks/SM fits 148*228KB? 64+2KB
// per block -> 3 blocks/SM, 512 blocks -> 1.16 waves. Acceptable: TMA reads
// drain fast (smem-side), wave 2 overlaps wave 1's write drain.
#undef TILE_FLOATS
#define TILE_FLOATS (D_DEVS * TOK_PER_BLK * E_PER_DEV)

__global__ __launch_bounds__(256) void moe_remap_mlp(
    const float* __restrict__ topk,     // [T, E]
    const int*   __restrict__ mapping,  // [E, D] one-hot
    const int*   __restrict__ meta,     // [T, K]
    float*       __restrict__ out,      // [D, T, 32]
    float*       __restrict__ mask,     // [T/2, D]
    int T)
{
    __shared__ __align__(128) float sdata[TILE_FLOATS];   // 64KB
    __shared__ int wcnt_s[64];
    __shared__ int C_s[64];
    __shared__ short invperm_s[E_EXPERTS];

    const int tid  = threadIdx.x;
    const int lane = tid & 31;
    const int warp = tid >> 5;
    const int blkT = blockIdx.x * TOK_PER_BLK;
    const int t0   = blkT + warp * 8;            // warp's first token (8 tokens)

    // ---- issue ALL independent global loads first (MLP = 4 per thread) ----
    const int e0 = meta[t0 * K_TOPK + lane];          // tokens t0..t0+3
    const int e1 = meta[t0 * K_TOPK + 32 + lane];     // tokens t0+4..t0+7
    const int4 a4 = reinterpret_cast<const int4*>(mapping)[tid * 2];
    const int4 b4 = reinterpret_cast<const int4*>(mapping)[tid * 2 + 1];

    const int tl = lane >> 3;                          // 0..3
    // dependent gathers — issue as soon as e0/e1 land
    const float gv0 = topk[(t0 + tl) * E_EXPERTS + e0];
    const float gv1 = topk[(t0 + 4 + tl) * E_EXPERTS + e1];

    // ---- invperm: argmax + ballot counts (thread tid = expert tid) ----
    int v8[8] = {a4.x, a4.y, a4.z, a4.w, b4.x, b4.y, b4.z, b4.w};
    int best = v8[0], d = 0;
#pragma unroll
    for (int i = 1; i < D_DEVS; i++)
        if (v8[i] > best) { best = v8[i]; d = i; }     // first max wins

    const unsigned lt = (1u << lane) - 1u;
    int within = 0, mycnt = 0;
#pragma unroll
    for (int d2 = 0; d2 < D_DEVS; d2++) {
        unsigned b = __ballot_sync(0xffffffffu, d == d2);
        if (d2 == d)    within = __popc(b & lt);
        if (lane == d2) mycnt  = __popc(b);
    }
    if (lane < D_DEVS) wcnt_s[warp * 8 + lane] = mycnt;

    // ---- zero 64KB tile: 4096 f4 / 256 thr = 16 STS.128 each ----
    {
        float4* s4 = reinterpret_cast<float4*>(sdata);
        const float4 z = make_float4(0.f, 0.f, 0.f, 0.f);
#pragma unroll
        for (int i = 0; i < 16; i++) s4[tid + 256 * i] = z;
    }
    __syncthreads();

    // ---- warp 0: exclusive scan of 64 counts in (device*8 + warp) order ----
    if (warp == 0) {
        int x0 = wcnt_s[(lane & 7) * 8 + (lane >> 3)];
        int x1 = wcnt_s[((lane + 32) & 7) * 8 + ((lane + 32) >> 3)];
        int i0 = x0, i1 = x1;
#pragma unroll
        for (int o = 1; o < 32; o <<= 1) {
            int y0 = __shfl_up_sync(0xffffffffu, i0, o);
            int y1 = __shfl_up_sync(0xffffffffu, i1, o);
            if (lane >= o) { i0 += y0; i1 += y1; }
        }
        const int tot0 = __shfl_sync(0xffffffffu, i0, 31);
        C_s[lane]      = i0 - x0;
        C_s[lane + 32] = i1 - x1 + tot0;
    }
    __syncthreads();
    invperm_s[tid] = (short)(C_s[d * 8 + warp] + within);
    __syncthreads();

    // ---- scatter both selections into smem tile ----
    const int p0 = invperm_s[e0], p1 = invperm_s[e1];
    const int d0s = p0 >> 5, j0 = p0 & 31;
    const int d1s = p1 >> 5, j1 = p1 & 31;
    const int tb0 = warp * 8 + tl;                 // token-in-block (0..63)
    const int tb1 = warp * 8 + 4 + tl;
    sdata[d0s * (TOK_PER_BLK * E_PER_DEV) + tb0 * E_PER_DEV + j0] = gv0;
    sdata[d1s * (TOK_PER_BLK * E_PER_DEV) + tb1 * E_PER_DEV + j1] = gv1;

    // ---- masks: 4 pairs per warp, packed dual butterfly (R5-verified) ----
    {
        unsigned mc = (1u << d0s) | ((1u << d1s) << 8);
        const unsigned pm = (lane < 16) ? 0x0000ffffu : 0xffff0000u;
        const unsigned r  = __reduce_or_sync(pm, mc);
        const unsigned other = __shfl_xor_sync(0xffffffffu, r, 16);
        const unsigned lo = (lane < 16) ? r : other;   // pairs (0, 2)
        const unsigned hi = (lane < 16) ? other : r;   // pairs (1, 3)

        const int pl = lane >> 3;
        const int dd = lane & 7;
        unsigned bits;
        if      (pl == 0) bits = lo & 0xffu;
        else if (pl == 1) bits = hi & 0xffu;
        else if (pl == 2) bits = (lo >> 8) & 0xffu;
        else              bits = (hi >> 8) & 0xffu;

        // warp covers pairs blkT/2 + warp*4 .. +3 -> 32 consecutive floats
        mask[blkT * 4 + warp * 32 + lane] = ((bits >> dd) & 1u) ? 1.0f : 0.0f;
    }

    // ---- publish tile to async proxy, bulk-store 8 x 8KB plane slices ----
    asm volatile("fence.proxy.async.shared::cta;" ::: "memory");
    __syncthreads();

    if (tid == 0) {
        uint32_t saddr;
        asm("{ .reg .u64 t; cvta.to.shared.u64 t, %1; cvt.u32.u64 %0, t; }"
            : "=r"(saddr) : "l"(sdata));
#pragma unroll
        for (int dd = 0; dd < D_DEVS; dd++) {
            float* gdst = out + dd * (T * E_PER_DEV) + blkT * E_PER_DEV;
            asm volatile(
                "cp.async.bulk.global.shared::cta.bulk_group [%0], [%1], %2;"
                :: "l"(gdst),
                   "r"(saddr + dd * (TOK_PER_BLK * E_PER_DEV * 4)),
                   "r"(TOK_PER_BLK * E_PER_DEV * 4)
                : "memory");
        }
        asm volatile("cp.async.bulk.commit_group;" ::: "memory");
        // hold CTA only until TMA has READ smem; writes drain async
        asm volatile("cp.async.bulk.wait_group.read 0;" ::: "memory");
    }
}

extern "C" void kernel_launch(void* const* d_in, const int* in_sizes, int n_in,
                              void* d_out, int out_size) {
    const float* topk    = (const float*)d_in[0];   // [1,1,T,E]
    const int*   mapping = (const int*)  d_in[1];   // [1,1,E,D]
    const int*   meta    = (const int*)  d_in[2];   // [1,1,T,K]

    const int T = in_sizes[0] / E_EXPERTS;          // 32768

    float* out  = (float*)d_out;                            // [D, T, 32]
    float* mask = out + (size_t)D_DEVS * T * E_PER_DEV;     // [T/2, D]

    const int blocks = T / TOK_PER_BLK;             // 512
    moe_remap_mlp<<<blocks, 256>>>(topk, mapping, meta, out, mask, T);
}